// round 12
// baseline (speedup 1.0000x reference)
#include <cuda_runtime.h>
#include <cuda_bf16.h>
#include <cstdint>
#include <math.h>

#define B     64
#define T     256
#define U     1024
#define G3    3072
#define NBLK  128
#define NT    512

// h packed in MMA A-fragment order:
// [par][ ((bt*64 + kk)*2 + half)*32 + lane ] -> uint4
__device__ __align__(16) uint4 g_hpk[2][4 * 64 * 2 * 32];
__device__ unsigned g_flag[8];          // per k-eighth counters (monotonic, per-warp arrivals)
__device__ unsigned g_bar_cnt, g_bar_gen;

// ---- SMEM layout (bytes) ----
#define SM_W     0
#define W_NSTR   2064
#define W_PSTR   49536
#define SM_REC   99072               // float [2 parity][8 plane][64][26]
#define REC_PAR  53248               // bytes per parity buffer
#define REC_PL   1664                // floats per plane
#define SMEM_TOTAL (99072 + 2*53248) // 205568

// ---- PTX helpers ----
__device__ __forceinline__ uint32_t smem_u32(const void* p) {
    uint32_t a;
    asm("{ .reg .u64 t; cvta.to.shared.u64 t, %1; cvt.u32.u64 %0, t; }" : "=r"(a) : "l"(p));
    return a;
}
__device__ __forceinline__ void ldsm2(uint32_t* r, uint32_t addr) {
    asm volatile("ldmatrix.sync.aligned.m8n8.x2.shared.b16 {%0,%1}, [%2];"
                 : "=r"(r[0]), "=r"(r[1]) : "r"(addr));
}
__device__ __forceinline__ void ldsm4(uint32_t* r, uint32_t addr) {
    asm volatile("ldmatrix.sync.aligned.m8n8.x4.shared.b16 {%0,%1,%2,%3}, [%4];"
                 : "=r"(r[0]), "=r"(r[1]), "=r"(r[2]), "=r"(r[3]) : "r"(addr));
}
__device__ __forceinline__ void mma4(float* c, const uint4& a, uint32_t b0, uint32_t b1) {
    asm volatile("mma.sync.aligned.m16n8k16.row.col.f32.bf16.bf16.f32 "
                 "{%0,%1,%2,%3}, {%4,%5,%6,%7}, {%8,%9}, {%0,%1,%2,%3};"
                 : "+f"(c[0]), "+f"(c[1]), "+f"(c[2]), "+f"(c[3])
                 : "r"(a.x), "r"(a.y), "r"(a.z), "r"(a.w), "r"(b0), "r"(b1));
}
__device__ __forceinline__ void wait_flag(unsigned* f, unsigned tgt) {
    unsigned g;
    while (1) {
        asm volatile("ld.acquire.gpu.u32 %0, [%1];" : "=r"(g) : "l"(f));
        if ((int)(g - tgt) >= 0) break;
        __nanosleep(16);
    }
}
__device__ __forceinline__ void arrive_flag(unsigned* f) {
    asm volatile("red.release.gpu.global.add.u32 [%0], 1;" :: "l"(f));
}

// startup-only grid barrier
__device__ __forceinline__ void grid_barrier() {
    __syncthreads();
    if (threadIdx.x == 0) {
        unsigned gen0;
        asm volatile("ld.acquire.gpu.u32 %0, [%1];" : "=r"(gen0) : "l"(&g_bar_gen));
        unsigned prev;
        asm volatile("atom.release.gpu.global.add.u32 %0, [%1], 1;" : "=r"(prev) : "l"(&g_bar_cnt));
        if (prev == NBLK - 1) {
            asm volatile("st.relaxed.gpu.global.u32 [%0], 0;" :: "l"(&g_bar_cnt));
            asm volatile("red.release.gpu.global.add.u32 [%0], 1;" :: "l"(&g_bar_gen));
        } else {
            unsigned g;
            do { asm volatile("ld.acquire.gpu.u32 %0, [%1];" : "=r"(g) : "l"(&g_bar_gen)); } while (g == gen0);
        }
    }
    __syncthreads();
}

// pack one unit (b, u0+uu): hi at off, lo at off+512
__device__ __forceinline__ void pack_unit(char* bufbase, uint32_t off, float v) {
    __nv_bfloat16 h = __float2bfloat16(v);
    __nv_bfloat16 lo = __float2bfloat16(v - __bfloat162float(h));
    *(unsigned short*)(bufbase + off)       = __bfloat16_as_ushort(h);
    *(unsigned short*)(bufbase + off + 512) = __bfloat16_as_ushort(lo);
}

__global__ void __launch_bounds__(NT, 1)
gru_all(const int* __restrict__ x, const float* __restrict__ hidden,
        const float* __restrict__ Win, const float* __restrict__ Wrec,
        const float* __restrict__ bin, const float* __restrict__ brec,
        float* __restrict__ out) {
    extern __shared__ __align__(1024) char smem[];
    const uint32_t sbase = smem_u32(smem);
    const int tid = threadIdx.x;
    const int wid = tid >> 5;
    const int l   = tid & 31;
    const int blk = blockIdx.x;
    const int u0  = blk * 8;

    // ---- one-time: W_rec slice -> bf16 hi/lo in SMEM [pass][n][k] ----
    for (int idx = tid; idx < 24 * U; idx += NT) {
        int k = idx / 24;
        int j = idx - k * 24;
        int gate = j >> 3, uu = j & 7;
        float w = Wrec[(size_t)k * G3 + gate * U + u0 + uu];
        __nv_bfloat16 hi = __float2bfloat16(w);
        __nv_bfloat16 lo = __float2bfloat16(w - __bfloat162float(hi));
        *(__nv_bfloat16*)(smem + SM_W + j * W_NSTR + k * 2) = hi;
        *(__nv_bfloat16*)(smem + SM_W + W_PSTR + j * W_NSTR + k * 2) = lo;
    }

    // ---- gate mapping: all 512 threads, 1 unit each: (b, uu) ----
    const int b  = tid >> 3;
    const int uu = tid & 7;
    const int btg = b >> 4, r_ = b & 15;
    const int kk_self = u0 >> 4;
    const uint32_t woff = (uint32_t)((r_ & 7) * 4 + ((uu >> 1) & 3)) * 16
                        + (uint32_t)((r_ >> 3) + 2 * ((u0 >> 3) & 1)) * 4
                        + (uu & 1) * 2;
    const uint32_t poff = (uint32_t)((btg * 64 + kk_self) * 2) * 512 + woff;

    // fused biases: z/r gates take bin+brec; h gate keeps them separate
    const float cz  = bin[0 * U + u0 + uu] + brec[0 * U + u0 + uu];
    const float cr  = bin[1 * U + u0 + uu] + brec[1 * U + u0 + uu];
    const float bih = bin[2 * U + u0 + uu];
    const float bhh = brec[2 * U + u0 + uu];
    float hold = hidden[(size_t)b * U + u0 + uu];
    int tok = x[b * T];

    // ---- warp MMA mapping: kq = wid>>1 (k-eighth), bth = wid&1 (batch half) ----
    const int kq  = wid >> 1;
    const int bth = wid & 1;
    const uint32_t boff4 = (uint32_t)((l >> 4) * 8 + (l & 7)) * W_NSTR + ((l >> 3) & 1) * 16;
    const uint32_t boff2 = (uint32_t)(l & 7) * W_NSTR + (l & 8) * 2;
    const int grp = blk >> 4;   // this CTA's producer flag group

    // capture flag base BEFORE anyone arrives (grid barrier orders this)
    unsigned fbase = *(volatile unsigned*)&g_flag[kq];
    grid_barrier();

    // publish h0 into buffer 0 (per-warp arrival)
    pack_unit((char*)g_hpk[0], poff, hold);
    __syncwarp();
    if (l == 0) arrive_flag(&g_flag[grp]);

    for (int t = 0; t < T; t++) {
        const int par = t & 1;
        float* rec_s = (float*)(smem + SM_REC + par * REC_PAR);

        // gate-input loads issued before the flag wait (latency overlap)
        const float* wrow = Win + (size_t)tok * G3 + u0 + uu;
        float xz = wrow[0], xr = wrow[U], xh = wrow[2 * U];
        int tok_n = (t + 1 < T) ? x[b * T + t + 1] : 0;

        // wait for the 256 producer warps of this warp's k-eighth
        if (l == 0) wait_flag(&g_flag[kq], fbase + 256u * (t + 1));
        __syncwarp();

        // ---- GEMM: 8 k-tiles, 2 batch-tiles (bt = 2*bth, 2*bth+1) ----
        float acc[2][3][4];
        #pragma unroll
        for (int bt = 0; bt < 2; bt++)
            #pragma unroll
            for (int nt = 0; nt < 3; nt++)
                #pragma unroll
                for (int e = 0; e < 4; e++) acc[bt][nt][e] = 0.f;

        const uint4* pA0 = g_hpk[par] + (size_t)(((2 * bth)     * 64 + kq * 8) * 2) * 32 + l;
        const uint4* pA1 = g_hpk[par] + (size_t)(((2 * bth + 1) * 64 + kq * 8) * 2) * 32 + l;

        uint4 Ah[2][2], Al[2][2];
        #pragma unroll
        for (int i = 0; i < 2; i++) {
            Ah[0][i] = __ldcg(pA0 + i * 64); Al[0][i] = __ldcg(pA0 + i * 64 + 32);
            Ah[1][i] = __ldcg(pA1 + i * 64); Al[1][i] = __ldcg(pA1 + i * 64 + 32);
        }

        #pragma unroll
        for (int kt = 0; kt < 8; kt++) {
            uint4 c0h = Ah[0][kt & 1], c0l = Al[0][kt & 1];
            uint4 c1h = Ah[1][kt & 1], c1l = Al[1][kt & 1];
            if (kt < 6) {
                Ah[0][kt & 1] = __ldcg(pA0 + (kt + 2) * 64);
                Al[0][kt & 1] = __ldcg(pA0 + (kt + 2) * 64 + 32);
                Ah[1][kt & 1] = __ldcg(pA1 + (kt + 2) * 64);
                Al[1][kt & 1] = __ldcg(pA1 + (kt + 2) * 64 + 32);
            }

            uint32_t wb = sbase + SM_W + (uint32_t)(kq * 8 + kt) * 32;
            uint32_t bh01[4], bh2[2], bl01[4], bl2[2];
            ldsm4(bh01, wb + boff4);
            ldsm2(bh2,  wb + 16 * W_NSTR + boff2);
            ldsm4(bl01, wb + W_PSTR + boff4);
            ldsm2(bl2,  wb + W_PSTR + 16 * W_NSTR + boff2);

            // term 1: h_hi @ W_hi  (6 independent accs)
            mma4(acc[0][0], c0h, bh01[0], bh01[1]);
            mma4(acc[0][1], c0h, bh01[2], bh01[3]);
            mma4(acc[0][2], c0h, bh2[0],  bh2[1]);
            mma4(acc[1][0], c1h, bh01[0], bh01[1]);
            mma4(acc[1][1], c1h, bh01[2], bh01[3]);
            mma4(acc[1][2], c1h, bh2[0],  bh2[1]);
            // term 2: h_hi @ W_lo
            mma4(acc[0][0], c0h, bl01[0], bl01[1]);
            mma4(acc[0][1], c0h, bl01[2], bl01[3]);
            mma4(acc[0][2], c0h, bl2[0],  bl2[1]);
            mma4(acc[1][0], c1h, bl01[0], bl01[1]);
            mma4(acc[1][1], c1h, bl01[2], bl01[3]);
            mma4(acc[1][2], c1h, bl2[0],  bl2[1]);
            // term 3: h_lo @ W_hi
            mma4(acc[0][0], c0l, bh01[0], bh01[1]);
            mma4(acc[0][1], c0l, bh01[2], bh01[3]);
            mma4(acc[0][2], c0l, bh2[0],  bh2[1]);
            mma4(acc[1][0], c1l, bh01[0], bh01[1]);
            mma4(acc[1][1], c1l, bh01[2], bh01[3]);
            mma4(acc[1][2], c1l, bh2[0],  bh2[1]);
        }

        // ---- epilogue: partials -> plane kq (parity buffer) ----
        {
            float* pl = rec_s + kq * REC_PL;
            int row = l >> 2, c2 = (l & 3) * 2;
            #pragma unroll
            for (int bt = 0; bt < 2; bt++) {
                int bb0 = (2 * bth + bt) * 16 + row;
                #pragma unroll
                for (int nt = 0; nt < 3; nt++) {
                    int j0 = nt * 8 + c2;
                    *(float2*)&pl[bb0 * 26 + j0]       = make_float2(acc[bt][nt][0], acc[bt][nt][1]);
                    *(float2*)&pl[(bb0 + 8) * 26 + j0] = make_float2(acc[bt][nt][2], acc[bt][nt][3]);
                }
            }
        }
        // parity-alternating named barrier: warps one step apart use different ids
        if (par == 0) asm volatile("bar.sync 1, %0;" :: "n"(NT) : "memory");
        else          asm volatile("bar.sync 2, %0;" :: "n"(NT) : "memory");

        // ---- gates: every thread, 1 unit ----
        {
            float rz = cz, rr = cr, rh = bhh;
            #pragma unroll
            for (int p = 0; p < 8; p++) {
                const float* pl = rec_s + p * REC_PL + b * 26;
                rz += pl[uu];
                rr += pl[8 + uu];
                rh += pl[16 + uu];
            }
            float z  = __fdividef(1.f, 1.f + __expf(-(xz + rz)));
            float r  = __fdividef(1.f, 1.f + __expf(-(xr + rr)));
            float ta = xh + bih + r * rh;
            float hh = 1.f - __fdividef(2.f, __expf(2.f * ta) + 1.f);
            float hn = z * hold + (1.f - z) * hh;
            hold = hn;
            pack_unit((char*)g_hpk[par ^ 1], poff, hn);
            __syncwarp();
            if (l == 0 && t < T - 1) arrive_flag(&g_flag[grp]);
            out[((size_t)b * T + t) * U + u0 + uu] = hn;
            if (t == T - 1)
                out[(size_t)B * T * U + (size_t)b * U + u0 + uu] = hn;
            tok = tok_n;
        }
    }
}

extern "C" void kernel_launch(void* const* d_in, const int* in_sizes, int n_in,
                              void* d_out, int out_size) {
    const int*   x      = (const int*)d_in[0];
    const float* hidden = (const float*)d_in[1];
    const float* Win    = (const float*)d_in[2];
    const float* Wrec   = (const float*)d_in[3];
    const float* bin    = (const float*)d_in[4];
    const float* brec   = (const float*)d_in[5];
    float* out = (float*)d_out;

    cudaFuncSetAttribute(gru_all, cudaFuncAttributeMaxDynamicSharedMemorySize, SMEM_TOTAL);
    gru_all<<<NBLK, NT, SMEM_TOTAL>>>(x, hidden, Win, Wrec, bin, brec, out);
}

// round 13
// speedup vs baseline: 1.8343x; 1.8343x over previous
#include <cuda_runtime.h>
#include <cuda_bf16.h>
#include <cstdint>
#include <math.h>

#define B     64
#define T     256
#define U     1024
#define G3    3072
#define NBLK  128
#define NT    512

// h packed in MMA A-fragment order:
// [par][ ((bt*64 + kk)*2 + half)*32 + lane ] -> uint4
__device__ __align__(16) uint4 g_hpk[2][4 * 64 * 2 * 32];
// per k-eighth dependency counters, padded to 128B so each lives on its own L2 line
__device__ __align__(128) unsigned g_flag[8 * 32];
__device__ unsigned g_bar_cnt, g_bar_gen;

// ---- SMEM layout (bytes) ----
#define SM_W     0
#define W_NSTR   2064
#define W_PSTR   49536
#define SM_REC   99072              // float [8 plane][64][26]
#define REC_PL   1664               // floats per plane
#define SMEM_TOTAL (99072 + 8*6656) // 152320

// ---- PTX helpers ----
__device__ __forceinline__ uint32_t smem_u32(const void* p) {
    uint32_t a;
    asm("{ .reg .u64 t; cvta.to.shared.u64 t, %1; cvt.u32.u64 %0, t; }" : "=r"(a) : "l"(p));
    return a;
}
__device__ __forceinline__ void ldsm2(uint32_t* r, uint32_t addr) {
    asm volatile("ldmatrix.sync.aligned.m8n8.x2.shared.b16 {%0,%1}, [%2];"
                 : "=r"(r[0]), "=r"(r[1]) : "r"(addr));
}
__device__ __forceinline__ void ldsm4(uint32_t* r, uint32_t addr) {
    asm volatile("ldmatrix.sync.aligned.m8n8.x4.shared.b16 {%0,%1,%2,%3}, [%4];"
                 : "=r"(r[0]), "=r"(r[1]), "=r"(r[2]), "=r"(r[3]) : "r"(addr));
}
__device__ __forceinline__ void mma4(float* c, const uint4& a, uint32_t b0, uint32_t b1) {
    asm volatile("mma.sync.aligned.m16n8k16.row.col.f32.bf16.bf16.f32 "
                 "{%0,%1,%2,%3}, {%4,%5,%6,%7}, {%8,%9}, {%0,%1,%2,%3};"
                 : "+f"(c[0]), "+f"(c[1]), "+f"(c[2]), "+f"(c[3])
                 : "r"(a.x), "r"(a.y), "r"(a.z), "r"(a.w), "r"(b0), "r"(b1));
}
__device__ __forceinline__ void wait_flag(unsigned* f, unsigned tgt) {
    unsigned g;
    while (1) {
        asm volatile("ld.acquire.gpu.u32 %0, [%1];" : "=r"(g) : "l"(f));
        if ((int)(g - tgt) >= 0) break;
        __nanosleep(32);
    }
}
__device__ __forceinline__ void arrive_flag(unsigned* f) {
    asm volatile("red.release.gpu.global.add.u32 [%0], 1;" :: "l"(f));
}

// startup-only grid barrier
__device__ __forceinline__ void grid_barrier() {
    __syncthreads();
    if (threadIdx.x == 0) {
        unsigned gen0;
        asm volatile("ld.acquire.gpu.u32 %0, [%1];" : "=r"(gen0) : "l"(&g_bar_gen));
        unsigned prev;
        asm volatile("atom.release.gpu.global.add.u32 %0, [%1], 1;" : "=r"(prev) : "l"(&g_bar_cnt));
        if (prev == NBLK - 1) {
            asm volatile("st.relaxed.gpu.global.u32 [%0], 0;" :: "l"(&g_bar_cnt));
            asm volatile("red.release.gpu.global.add.u32 [%0], 1;" :: "l"(&g_bar_gen));
        } else {
            unsigned g;
            do { asm volatile("ld.acquire.gpu.u32 %0, [%1];" : "=r"(g) : "l"(&g_bar_gen)); } while (g == gen0);
        }
    }
    __syncthreads();
}

// pack one unit (b, u0+uu): hi at off, lo at off+512
__device__ __forceinline__ void pack_unit(char* bufbase, uint32_t off, float v) {
    __nv_bfloat16 h = __float2bfloat16(v);
    __nv_bfloat16 lo = __float2bfloat16(v - __bfloat162float(h));
    *(unsigned short*)(bufbase + off)       = __bfloat16_as_ushort(h);
    *(unsigned short*)(bufbase + off + 512) = __bfloat16_as_ushort(lo);
}

__global__ void __launch_bounds__(NT, 1)
gru_all(const int* __restrict__ x, const float* __restrict__ hidden,
        const float* __restrict__ Win, const float* __restrict__ Wrec,
        const float* __restrict__ bin, const float* __restrict__ brec,
        float* __restrict__ out) {
    extern __shared__ __align__(1024) char smem[];
    const uint32_t sbase = smem_u32(smem);
    float* rec_s = (float*)(smem + SM_REC);
    const int tid = threadIdx.x;
    const int wid = tid >> 5;
    const int l   = tid & 31;
    const int blk = blockIdx.x;
    const int u0  = blk * 8;

    // ---- one-time: W_rec slice -> bf16 hi/lo in SMEM [pass][n][k] ----
    for (int idx = tid; idx < 24 * U; idx += NT) {
        int k = idx / 24;
        int j = idx - k * 24;
        int gate = j >> 3, uu = j & 7;
        float w = Wrec[(size_t)k * G3 + gate * U + u0 + uu];
        __nv_bfloat16 hi = __float2bfloat16(w);
        __nv_bfloat16 lo = __float2bfloat16(w - __bfloat162float(hi));
        *(__nv_bfloat16*)(smem + SM_W + j * W_NSTR + k * 2) = hi;
        *(__nv_bfloat16*)(smem + SM_W + W_PSTR + j * W_NSTR + k * 2) = lo;
    }

    // ---- gate mapping: all 512 threads, 1 unit each: (b, uu) ----
    const int b  = tid >> 3;
    const int uu = tid & 7;
    const int btg = b >> 4, r_ = b & 15;
    const int kk_self = u0 >> 4;
    const uint32_t woff = (uint32_t)((r_ & 7) * 4 + ((uu >> 1) & 3)) * 16
                        + (uint32_t)((r_ >> 3) + 2 * ((u0 >> 3) & 1)) * 4
                        + (uu & 1) * 2;
    const uint32_t poff = (uint32_t)((btg * 64 + kk_self) * 2) * 512 + woff;

    // fused biases: z/r gates take bin+brec; h gate keeps them separate
    const float cz  = bin[0 * U + u0 + uu] + brec[0 * U + u0 + uu];
    const float cr  = bin[1 * U + u0 + uu] + brec[1 * U + u0 + uu];
    const float bih = bin[2 * U + u0 + uu];
    const float bhh = brec[2 * U + u0 + uu];
    float hold = hidden[(size_t)b * U + u0 + uu];
    int tok = x[b * T];

    // ---- warp MMA mapping: kq = wid>>1 (k-eighth), bth = wid&1 (batch half) ----
    const int kq  = wid >> 1;
    const int bth = wid & 1;
    const uint32_t boff4 = (uint32_t)((l >> 4) * 8 + (l & 7)) * W_NSTR + ((l >> 3) & 1) * 16;
    const uint32_t boff2 = (uint32_t)(l & 7) * W_NSTR + (l & 8) * 2;
    const int grp = blk >> 4;   // this CTA's producer flag group

    // capture flag base BEFORE anyone arrives (grid barrier orders this)
    unsigned fbase = *(volatile unsigned*)&g_flag[kq * 32];
    grid_barrier();

    // publish h0 into buffer 0
    pack_unit((char*)g_hpk[0], poff, hold);
    __syncthreads();
    if (tid == 0) arrive_flag(&g_flag[grp * 32]);

    for (int t = 0; t < T; t++) {
        const int par = t & 1;

        // gate-input loads issued before the flag wait (latency overlap)
        const float* wrow = Win + (size_t)tok * G3 + u0 + uu;
        float xz = wrow[0], xr = wrow[U], xh = wrow[2 * U];
        int tok_n = (t + 1 < T) ? x[b * T + t + 1] : 0;

        // wait for the 16 producer CTAs of this warp's k-eighth
        if (l == 0) wait_flag(&g_flag[kq * 32], fbase + 16u * (t + 1));
        __syncwarp();

        // ---- GEMM: 8 k-tiles, 2 batch-tiles (bt = 2*bth, 2*bth+1) ----
        float acc[2][3][4];
        #pragma unroll
        for (int bt = 0; bt < 2; bt++)
            #pragma unroll
            for (int nt = 0; nt < 3; nt++)
                #pragma unroll
                for (int e = 0; e < 4; e++) acc[bt][nt][e] = 0.f;

        const uint4* pA0 = g_hpk[par] + (size_t)(((2 * bth)     * 64 + kq * 8) * 2) * 32 + l;
        const uint4* pA1 = g_hpk[par] + (size_t)(((2 * bth + 1) * 64 + kq * 8) * 2) * 32 + l;

        uint4 Ah[2][2], Al[2][2];
        #pragma unroll
        for (int i = 0; i < 2; i++) {
            Ah[0][i] = __ldcg(pA0 + i * 64); Al[0][i] = __ldcg(pA0 + i * 64 + 32);
            Ah[1][i] = __ldcg(pA1 + i * 64); Al[1][i] = __ldcg(pA1 + i * 64 + 32);
        }

        #pragma unroll
        for (int kt = 0; kt < 8; kt++) {
            uint32_t wb = sbase + SM_W + (uint32_t)(kq * 8 + kt) * 32;
            uint32_t bh01[4], bl01[4], bh2[2], bl2[2];
            ldsm4(bh01, wb + boff4);
            ldsm2(bh2,  wb + 16 * W_NSTR + boff2);
            ldsm4(bl01, wb + W_PSTR + boff4);
            ldsm2(bl2,  wb + W_PSTR + 16 * W_NSTR + boff2);

            uint4 c0h = Ah[0][kt & 1], c0l = Al[0][kt & 1];
            uint4 c1h = Ah[1][kt & 1], c1l = Al[1][kt & 1];
            if (kt < 6) {
                Ah[0][kt & 1] = __ldcg(pA0 + (kt + 2) * 64);
                Al[0][kt & 1] = __ldcg(pA0 + (kt + 2) * 64 + 32);
                Ah[1][kt & 1] = __ldcg(pA1 + (kt + 2) * 64);
                Al[1][kt & 1] = __ldcg(pA1 + (kt + 2) * 64 + 32);
            }

            mma4(acc[0][0], c0h, bh01[0], bh01[1]);
            mma4(acc[0][1], c0h, bh01[2], bh01[3]);
            mma4(acc[0][2], c0h, bh2[0],  bh2[1]);
            mma4(acc[0][0], c0h, bl01[0], bl01[1]);
            mma4(acc[0][1], c0h, bl01[2], bl01[3]);
            mma4(acc[0][2], c0h, bl2[0],  bl2[1]);
            mma4(acc[0][0], c0l, bh01[0], bh01[1]);
            mma4(acc[0][1], c0l, bh01[2], bh01[3]);
            mma4(acc[0][2], c0l, bh2[0],  bh2[1]);

            mma4(acc[1][0], c1h, bh01[0], bh01[1]);
            mma4(acc[1][1], c1h, bh01[2], bh01[3]);
            mma4(acc[1][2], c1h, bh2[0],  bh2[1]);
            mma4(acc[1][0], c1h, bl01[0], bl01[1]);
            mma4(acc[1][1], c1h, bl01[2], bl01[3]);
            mma4(acc[1][2], c1h, bl2[0],  bl2[1]);
            mma4(acc[1][0], c1l, bh01[0], bh01[1]);
            mma4(acc[1][1], c1l, bh01[2], bh01[3]);
            mma4(acc[1][2], c1l, bh2[0],  bh2[1]);
        }

        // ---- epilogue: partials -> plane kq, rows [32*bth, 32*bth+32) ----
        {
            float* pl = rec_s + kq * REC_PL;
            int row = l >> 2, c2 = (l & 3) * 2;
            #pragma unroll
            for (int bt = 0; bt < 2; bt++) {
                int bb0 = (2 * bth + bt) * 16 + row;
                #pragma unroll
                for (int nt = 0; nt < 3; nt++) {
                    int j0 = nt * 8 + c2;
                    *(float2*)&pl[bb0 * 26 + j0]       = make_float2(acc[bt][nt][0], acc[bt][nt][1]);
                    *(float2*)&pl[(bb0 + 8) * 26 + j0] = make_float2(acc[bt][nt][2], acc[bt][nt][3]);
                }
            }
        }
        __syncthreads();

        // ---- gates: every thread, 1 unit ----
        {
            float rz = cz, rr = cr, rh = bhh;
            #pragma unroll
            for (int p = 0; p < 8; p++) {
                const float* pl = rec_s + p * REC_PL + b * 26;
                rz += pl[uu];
                rr += pl[8 + uu];
                rh += pl[16 + uu];
            }
            float z  = __fdividef(1.f, 1.f + __expf(-(xz + rz)));
            float r  = __fdividef(1.f, 1.f + __expf(-(xr + rr)));
            float ta = xh + bih + r * rh;
            float hh = 1.f - __fdividef(2.f, __expf(2.f * ta) + 1.f);
            float hn = z * hold + (1.f - z) * hh;
            hold = hn;
            pack_unit((char*)g_hpk[par ^ 1], poff, hn);
            __syncthreads();
            if (tid == 0 && t < T - 1) arrive_flag(&g_flag[grp * 32]);
            out[((size_t)b * T + t) * U + u0 + uu] = hn;
            if (t == T - 1)
                out[(size_t)B * T * U + (size_t)b * U + u0 + uu] = hn;
            tok = tok_n;
        }
    }
}

extern "C" void kernel_launch(void* const* d_in, const int* in_sizes, int n_in,
                              void* d_out, int out_size) {
    const int*   x      = (const int*)d_in[0];
    const float* hidden = (const float*)d_in[1];
    const float* Win    = (const float*)d_in[2];
    const float* Wrec   = (const float*)d_in[3];
    const float* bin    = (const float*)d_in[4];
    const float* brec   = (const float*)d_in[5];
    float* out = (float*)d_out;

    cudaFuncSetAttribute(gru_all, cudaFuncAttributeMaxDynamicSharedMemorySize, SMEM_TOTAL);
    gru_all<<<NBLK, NT, SMEM_TOTAL>>>(x, hidden, Win, Wrec, bin, brec, out);
}